// round 1
// baseline (speedup 1.0000x reference)
#include <cuda_runtime.h>
#include <math.h>

// Problem constants (fixed shapes from setup_inputs)
#define BB    8
#define HIDC  64
#define NLAY  4
#define TT    19        // in_len + out_len - 1
#define INLEN 10
#define NPX   1024      // 32*32
#define LS    (BB*HIDC*NPX)   // 524288 floats per (B,64,32,32) tensor

// ---------------- scratch (device globals; no allocation at runtime) ----------------
__device__ float g_xp[INLEN*LS];     // patched input (t,b,64,32,32)
__device__ float g_h[NLAY*LS];
__device__ float g_c[NLAY*LS];
__device__ float g_m[LS];
__device__ float g_mem[2*LS];        // (b,128,32,32)
__device__ float g_xc[7*LS];         // (b,448,32,32)
__device__ float g_hc[4*LS];         // (b,256,32,32)
__device__ float g_mc[3*LS];         // (b,192,32,32)
__device__ float g_oc[LS];
__device__ float g_lc[LS];
__device__ float g_outs[TT*LS];      // (t,b,64,32,32)

__device__ __forceinline__ float sigf(float v) { return 1.0f / (1.0f + expf(-v)); }

// =====================================================================
// Generic direct 3x3 SAME conv over a 32x32 image, NCHW.
// Block: 128 threads, covers (32/SP rows) x 32 cols x 16 out-channels.
// Thread tile: PPT pixels x 8 channels in registers.
// =====================================================================
template<int CI, int SP, int EPI>
__device__ __forceinline__ void conv_body(
    const float* __restrict__ in,    // (CI,32,32) image base
    const float* __restrict__ w,     // (CO,CI,3,3) base (co0 applied inside)
    const float* __restrict__ bias,  // (CO)
    float* __restrict__ out,         // EPI=0: (CO,32,32) image base; EPI=1: (256,256) output image base
    int co0, int sp)
{
    constexpr int ROWS = 32 / SP;
    constexpr int HR   = ROWS + 2;
    constexpr int PPT  = (ROWS * 32) / 64;   // 8 for SP=2, 4 for SP=4
    __shared__ float s_in[8][HR * 34];
    __shared__ float s_w[16][8 * 9];

    const int tid  = threadIdx.x;
    const int cob  = (tid >> 6) << 3;   // 0 or 8
    const int pxg  = tid & 63;
    const int lc   = pxg & 31;
    const int lr0  = pxg >> 5;          // 0 or 1
    const int row0 = sp * ROWS;

    float bv[8];
#pragma unroll
    for (int c2 = 0; c2 < 8; c2++) bv[c2] = bias[co0 + cob + c2];
    float acc[PPT][8];
#pragma unroll
    for (int p = 0; p < PPT; p++)
#pragma unroll
        for (int c2 = 0; c2 < 8; c2++) acc[p][c2] = bv[c2];

    for (int ci0 = 0; ci0 < CI; ci0 += 8) {
        // stage input chunk with halo (zero-padded)
        for (int idx = tid; idx < 8 * HR * 34; idx += 128) {
            int ci  = idx / (HR * 34);
            int rem = idx - ci * (HR * 34);
            int r   = rem / 34;
            int cc2 = rem - r * 34;
            int gr = row0 + r - 1, gc = cc2 - 1;
            float v = 0.f;
            if ((unsigned)gr < 32u && (unsigned)gc < 32u)
                v = in[(ci0 + ci) * NPX + gr * 32 + gc];
            s_in[ci][rem] = v;
        }
        // stage weights: 16co x 8ci x 9
        for (int idx = tid; idx < 16 * 72; idx += 128) {
            int c2  = idx / 72;
            int rem = idx - c2 * 72;      // ci*9+tap within chunk
            s_w[c2][rem] = w[(co0 + c2) * CI * 9 + ci0 * 9 + rem];
        }
        __syncthreads();

#pragma unroll 1
        for (int ci = 0; ci < 8; ci++) {
#pragma unroll
            for (int dy = 0; dy < 3; dy++) {
#pragma unroll
                for (int dx = 0; dx < 3; dx++) {
                    float wv[8];
#pragma unroll
                    for (int c2 = 0; c2 < 8; c2++)
                        wv[c2] = s_w[cob + c2][ci * 9 + dy * 3 + dx];
#pragma unroll
                    for (int p = 0; p < PPT; p++) {
                        float iv = s_in[ci][(lr0 + 2 * p + dy) * 34 + lc + dx];
#pragma unroll
                        for (int c2 = 0; c2 < 8; c2++)
                            acc[p][c2] = fmaf(iv, wv[c2], acc[p][c2]);
                    }
                }
            }
        }
        __syncthreads();
    }

    if (EPI == 0) {
#pragma unroll
        for (int p = 0; p < PPT; p++) {
            int gpx = (row0 + lr0 + 2 * p) * 32 + lc;
#pragma unroll
            for (int c2 = 0; c2 < 8; c2++)
                out[(co0 + cob + c2) * NPX + gpx] = acc[p][c2];
        }
    } else {
        // decoder: sigmoid + depth-to-space 8x8 into (256,256) image
#pragma unroll
        for (int p = 0; p < PPT; p++) {
            int gr = row0 + lr0 + 2 * p;   // patch row i
#pragma unroll
            for (int c2 = 0; c2 < 8; c2++) {
                int co = co0 + cob + c2;
                out[((co >> 3) * 32 + gr) * 256 + ((co & 7) << 5) + lc] =
                    sigf(acc[p][c2]);
            }
        }
    }
}

// ---- fused xc/hc/mc conv: grid = B * 56 groups * 2 spatial = 896 blocks ----
__global__ __launch_bounds__(128) void conv_xhm_k(
    const float* __restrict__ xin, const float* __restrict__ hin, const float* __restrict__ minb,
    const float* __restrict__ wx, const float* __restrict__ bx, float* __restrict__ xc,
    const float* __restrict__ wh, const float* __restrict__ bh, float* __restrict__ hc,
    const float* __restrict__ wm, const float* __restrict__ bm, float* __restrict__ mc)
{
    int bi = blockIdx.x;
    int sp = bi & 1; bi >>= 1;
    int g  = bi % 56;
    int b  = bi / 56;
    const float* in; const float* w; const float* bias; float* out; int co0; int cotot;
    if (g < 28)      { in = xin;  w = wx; bias = bx; out = xc; co0 = g * 16;        cotot = 448; }
    else if (g < 44) { in = hin;  w = wh; bias = bh; out = hc; co0 = (g - 28) * 16; cotot = 256; }
    else             { in = minb; w = wm; bias = bm; out = mc; co0 = (g - 44) * 16; cotot = 192; }
    conv_body<64, 2, 0>(in + (size_t)b * 64 * NPX, w, bias,
                        out + (size_t)b * cotot * NPX, co0, sp);
}

// ---- Wo conv: CI=128, CO=64, 4-way spatial split: grid = 8*4*4 = 128 ----
__global__ __launch_bounds__(128) void conv_oc_k(
    const float* __restrict__ mem, const float* __restrict__ wo,
    const float* __restrict__ bo, float* __restrict__ oc)
{
    int bi = blockIdx.x;
    int sp  = bi & 3;
    int cog = (bi >> 2) & 3;
    int b   = bi >> 4;
    conv_body<128, 4, 0>(mem + (size_t)b * 128 * NPX, wo, bo,
                         oc + (size_t)b * 64 * NPX, cog * 16, sp);
}

// ---- decoder conv: 152 images * 4 cog * 2 sp = 1216 blocks ----
__global__ __launch_bounds__(128) void conv_dec_k(
    const float* __restrict__ outs, const float* __restrict__ wd,
    const float* __restrict__ bd, float* __restrict__ dout)
{
    int bi = blockIdx.x;
    int sp  = bi & 1;
    int cog = (bi >> 1) & 3;
    int img = bi >> 3;          // 0..151, img = t*8 + b
    int t = img >> 3, b = img & 7;
    conv_body<64, 2, 1>(outs + (size_t)img * 64 * NPX, wd, bd,
                        dout + (size_t)(b * TT + t) * 65536, cog * 16, sp);
}

// ---- Wl 1x1 conv: grid = 8*4*2 = 64 blocks ----
__global__ __launch_bounds__(128) void conv1x1_k(
    const float* __restrict__ in, const float* __restrict__ w,
    const float* __restrict__ bias, float* __restrict__ out)
{
    __shared__ float s_w[16][128];
    int bi = blockIdx.x;
    int sp  = bi & 1;
    int cog = (bi >> 1) & 3;
    int b   = bi >> 3;
    int co0 = cog * 16;
    int tid = threadIdx.x;
    for (int i = tid; i < 16 * 128; i += 128) {
        int cc = i >> 7, ci = i & 127;
        s_w[cc][ci] = w[(co0 + cc) * 128 + ci];
    }
    __syncthreads();
    int cob = (tid >> 6) << 3;
    int pxg = tid & 63;
    const float* inb = in + (size_t)b * 128 * NPX + sp * 512 + pxg;
    float acc[8][8];
#pragma unroll
    for (int p = 0; p < 8; p++)
#pragma unroll
        for (int c2 = 0; c2 < 8; c2++) acc[p][c2] = bias[co0 + cob + c2];
#pragma unroll 1
    for (int ci = 0; ci < 128; ci++) {
        float wv[8];
#pragma unroll
        for (int c2 = 0; c2 < 8; c2++) wv[c2] = s_w[cob + c2][ci];
        const float* ip = inb + ci * NPX;
#pragma unroll
        for (int p = 0; p < 8; p++) {
            float iv = ip[64 * p];
#pragma unroll
            for (int c2 = 0; c2 < 8; c2++) acc[p][c2] = fmaf(iv, wv[c2], acc[p][c2]);
        }
    }
    float* ob = out + (size_t)b * 64 * NPX + sp * 512 + pxg;
#pragma unroll
    for (int p = 0; p < 8; p++)
#pragma unroll
        for (int c2 = 0; c2 < 8; c2++)
            ob[(co0 + cob + c2) * NPX + 64 * p] = acc[p][c2];
}

// ---- gate 1: i,f,g / i',f',g' -> c_new, m_new, mem ----
__global__ void gate1_k(const float* __restrict__ xc, const float* __restrict__ hc,
                        const float* __restrict__ mc, float* __restrict__ c,
                        float* __restrict__ m, float* __restrict__ mem)
{
    int idx = blockIdx.x * 256 + threadIdx.x;   // < 524288
    int px = idx & 1023;
    int ch = (idx >> 10) & 63;
    int b  = idx >> 16;
    const float* xcb = xc + (size_t)b * 448 * NPX;
    const float* hcb = hc + (size_t)b * 256 * NPX;
    const float* mcb = mc + (size_t)b * 192 * NPX;
    int o = ch * NPX + px;
    float ix  = xcb[o];              float fx  = xcb[o + 1 * 65536];
    float gx  = xcb[o + 2 * 65536];  float ixp = xcb[o + 3 * 65536];
    float fxp = xcb[o + 4 * 65536];  float gxp = xcb[o + 5 * 65536];
    float ih = hcb[o], fh = hcb[o + 65536], gh = hcb[o + 2 * 65536];
    float im = mcb[o], fm = mcb[o + 65536], gm = mcb[o + 2 * 65536];
    float it = sigf(ix + ih);
    float ft = sigf(fx + fh);
    float gt = tanhf(gx + gh);
    float cn = ft * c[idx] + it * gt;
    float itp = sigf(ixp + im);
    float ftp = sigf(fxp + fm);
    float gtp = tanhf(gxp + gm);
    float mn = ftp * m[idx] + itp * gtp;
    c[idx] = cn;
    m[idx] = mn;
    float* memb = mem + (size_t)b * 128 * NPX;
    memb[o]         = cn;
    memb[o + 65536] = mn;
}

// ---- gate 2: o_t, h_new ----
__global__ void gate2_k(const float* __restrict__ xc, const float* __restrict__ hc,
                        const float* __restrict__ oc, const float* __restrict__ lc,
                        float* __restrict__ h, float* __restrict__ out2)
{
    int idx = blockIdx.x * 256 + threadIdx.x;
    int px = idx & 1023;
    int ch = (idx >> 10) & 63;
    int b  = idx >> 16;
    int o  = ch * NPX + px;
    float ox = xc[(size_t)b * 448 * NPX + o + 6 * 65536];
    float oh = hc[(size_t)b * 256 * NPX + o + 3 * 65536];
    float ot = sigf(ox + oh + oc[idx]);
    float hv = ot * tanhf(lc[idx]);
    h[idx] = hv;
    if (out2) out2[idx] = hv;
}

// ---- patch (space-to-depth 8x8) ----
__global__ void patch_k(const float* __restrict__ x, float* __restrict__ xp)
{
    int idx = blockIdx.x * 256 + threadIdx.x;   // < 10*8*64*1024 = 5242880
    int px = idx & 1023;
    int ch = (idx >> 10) & 63;
    int b  = (idx >> 16) & 7;
    int t  = idx >> 19;
    int H = ((ch >> 3) << 5) + (px >> 5);
    int W = ((ch & 7) << 5) + (px & 31);
    xp[(size_t)(t * 8 + b) * 65536 + ch * NPX + px] =
        x[(size_t)(b * INLEN + t) * 65536 + H * 256 + W];
}

__global__ void zero_k(float* __restrict__ p, int n)
{
    int i = blockIdx.x * 256 + threadIdx.x;
    if (i < n) p[i] = 0.f;
}

// =====================================================================
extern "C" void kernel_launch(void* const* d_in, const int* in_sizes, int n_in,
                              void* d_out, int out_size)
{
    const float* x  = (const float*)d_in[0];
    const float* Wx = (const float*)d_in[3];
    const float* bx = (const float*)d_in[4];
    const float* Wh = (const float*)d_in[5];
    const float* bh = (const float*)d_in[6];
    const float* Wm = (const float*)d_in[7];
    const float* bm = (const float*)d_in[8];
    const float* Wo = (const float*)d_in[9];
    const float* bo = (const float*)d_in[10];
    const float* Wl = (const float*)d_in[11];
    const float* bl = (const float*)d_in[12];
    const float* Wd = (const float*)d_in[13];
    const float* bd = (const float*)d_in[14];
    float* out = (float*)d_out;

    float *xp, *h, *c, *m, *mem, *xc, *hc, *mc, *oc, *lc, *outs;
    cudaGetSymbolAddress((void**)&xp,   g_xp);
    cudaGetSymbolAddress((void**)&h,    g_h);
    cudaGetSymbolAddress((void**)&c,    g_c);
    cudaGetSymbolAddress((void**)&m,    g_m);
    cudaGetSymbolAddress((void**)&mem,  g_mem);
    cudaGetSymbolAddress((void**)&xc,   g_xc);
    cudaGetSymbolAddress((void**)&hc,   g_hc);
    cudaGetSymbolAddress((void**)&mc,   g_mc);
    cudaGetSymbolAddress((void**)&oc,   g_oc);
    cudaGetSymbolAddress((void**)&lc,   g_lc);
    cudaGetSymbolAddress((void**)&outs, g_outs);

    // zero states
    zero_k<<<(NLAY * LS + 255) / 256, 256>>>(h, NLAY * LS);
    zero_k<<<(NLAY * LS + 255) / 256, 256>>>(c, NLAY * LS);
    zero_k<<<(LS + 255) / 256, 256>>>(m, LS);

    // patch division
    patch_k<<<(INLEN * LS) / 256, 256>>>(x, xp);

    for (int t = 0; t < TT; t++) {
        const float* cur = (t < INLEN) ? (xp + (size_t)t * LS)
                                       : (outs + (size_t)(t - 1) * LS);
        for (int l = 0; l < NLAY; l++) {
            const float* inx = (l == 0) ? cur : (h + (size_t)(l - 1) * LS);
            conv_xhm_k<<<8 * 56 * 2, 128>>>(
                inx, h + (size_t)l * LS, m,
                Wx + (size_t)l * 448 * 64 * 9, bx + l * 448, xc,
                Wh + (size_t)l * 256 * 64 * 9, bh + l * 256, hc,
                Wm + (size_t)l * 192 * 64 * 9, bm + l * 192, mc);
            gate1_k<<<2048, 256>>>(xc, hc, mc, c + (size_t)l * LS, m, mem);
            conv_oc_k<<<8 * 4 * 4, 128>>>(mem, Wo + (size_t)l * 64 * 128 * 9,
                                          bo + l * 64, oc);
            conv1x1_k<<<8 * 4 * 2, 128>>>(mem, Wl + (size_t)l * 64 * 128,
                                          bl + l * 64, lc);
            gate2_k<<<2048, 256>>>(xc, hc, oc, lc, h + (size_t)l * LS,
                                   (l == 3) ? (outs + (size_t)t * LS) : nullptr);
        }
    }

    // decoder conv + sigmoid + depth-to-space
    conv_dec_k<<<152 * 4 * 2, 128>>>(outs, Wd, bd, out);
}